// round 15
// baseline (speedup 1.0000x reference)
#include <cuda_runtime.h>
#include <math.h>

#define BLOCK 256
#define K 16
#define NW (BLOCK / 32)      // 8 warps
#define FP_SCALE 65536.f     // 2^16 fixed-point scale (overflow-audited below)

// sm_103 integer REDUX: single-instruction warp reductions.
__device__ __forceinline__ int redux_add_s32(int v) {
    int r;
    asm volatile("redux.sync.add.s32 %0, %1, 0xffffffff;" : "=r"(r) : "r"(v));
    return r;
}
__device__ __forceinline__ unsigned redux_max_u32(unsigned v) {
    unsigned r;
    asm volatile("redux.sync.max.u32 %0, %1, 0xffffffff;" : "=r"(r) : "r"(v));
    return r;
}
__device__ __forceinline__ unsigned redux_min_u32(unsigned v) {
    unsigned r;
    asm volatile("redux.sync.min.u32 %0, %1, 0xffffffff;" : "=r"(r) : "r"(v));
    return r;
}

__global__ void __launch_bounds__(BLOCK, 1)
spectral_rank2_kernel(const float4* __restrict__ in4, float4* __restrict__ out4) {
    __shared__ int si[2][NW];        // fixed-point Sc, Ss warp partials
    __shared__ unsigned sq[2][NW];   // qmax, qmin warp partials (float bits)
    const int t = threadIdx.x;
    const int lane = t & 31, w = t >> 5;

    // ---- Phase 1: 4 x float4 loads (MLP=4) + feature transform.
    // sigmoid(|x|)=1/(1+e), v~=e, e=exp(-|x|); normalized feature direction
    // (1,q)/sqrt(1+q^2), q = e + e^2 > 0.
    float4 xv[4];
#pragma unroll
    for (int i = 0; i < 4; i++) xv[i] = in4[t + i * BLOCK];

    float q[K], cw[K];
    float pc = 0.f, ps = 0.f;
    unsigned pqmx = 0u, pqmn = 0xffffffffu;
#pragma unroll
    for (int k = 0; k < K; k++) {
        float x  = ((const float*)xv)[k];
        float e  = __expf(-fabsf(x));
        float qq = fmaf(e, e, e);                  // q = e + e^2
        float c  = rsqrtf(fmaf(qq, qq, 1.f));
        q[k] = qq; cw[k] = c;
        pc += c;
        ps = fmaf(qq, c, ps);
        unsigned qb = __float_as_uint(qq);
        pqmx = max(pqmx, qb);
        pqmn = min(pqmn, qb);
    }

    // ---- R1 (the only reduction round): fixed-point sums via REDUX.ADD.S32,
    // extremes via REDUX.{MAX,MIN}.U32 (positive-float bits are
    // order-isomorphic to u32). One barrier, two single-instruction levels.
    // Overflow audit: block totals <= 4096 -> level-2 value
    // <= 4 (replicas) * 4096 * 2^16 = 2^30 < INT32_MAX.
    {
        int ia = redux_add_s32(__float2int_rn(pc * FP_SCALE));
        int ib = redux_add_s32(__float2int_rn(ps * FP_SCALE));
        unsigned m = redux_max_u32(pqmx);
        unsigned n = redux_min_u32(pqmn);
        if (lane == 0) { si[0][w] = ia; si[1][w] = ib; sq[0][w] = m; sq[1][w] = n; }
    }
    __syncthreads();
    // Level 2: all 32 lanes read the 8 partials replicated 4x; REDUX sums the
    // replicas too -> total is 4x, folded into the 2^-18 constant. Integer
    // adds are order-independent -> fully deterministic across replays.
    const float Sc = (float)redux_add_s32(si[0][lane & 7]) * (0x1p-18f);
    const float Ss = (float)redux_add_s32(si[1][lane & 7]) * (0x1p-18f);
    const float qmx = __uint_as_float(redux_max_u32(sq[0][lane & 7]));
    const float qmn = __uint_as_float(redux_min_u32(sq[1][lane & 7]));

    // ---- Closed form (no further reductions): the rank-2 Gram matrix has
    // Perron eigenvector exactly (Sc, Ss) (identity: A*Sc+B*Ss=Sc,
    // B*Sc+G*Ss=Ss), so the Fiedler direction is the orthogonal complement
    // (al, be) = (-Ss, Sc). F(q) ∝ sin(θ-φ)/sqrt(cos(θ-φ)), θ = atan q —
    // strictly increasing, so extremes are at qmn/qmx (evaluated with the
    // identical op sequence for bit-consistent min/max).
    const float al = -Ss, be = Sc;
    float Fe[2];
    float qe[2] = {qmn, qmx};
#pragma unroll
    for (int k = 0; k < 2; k++) {
        float c    = rsqrtf(fmaf(qe[k], qe[k], 1.f));
        float d    = fmaf(qe[k], Ss, Sc) * c;
        float cdis = c * rsqrtf(d);
        Fe[k] = fmaf(be, qe[k], al) * cdis;
    }
    float Fmn = Fe[0], Fmx = Fe[1];              // monotone increasing in q
    float pivot = (fabsf(Fmx) >= fabsf(Fmn)) ? Fmx : Fmn;
    float sgn = (pivot >= 0.f) ? 1.f : -1.f;
    float mn = (sgn > 0.f) ? Fmn : -Fmx;
    float mx = (sgn > 0.f) ? Fmx : -Fmn;
    float scale = __fdividef(1.f, mx - mn + 1e-10f);
    float a1 = sgn * scale, a0 = -mn * scale;
    const float alp = al * a1, bep = be * a1;    // out = (bep*q+alp)*cdis + a0

    // ---- Epilogue: per-element Fiedler value + fused normalize + store.
    float r[K];
#pragma unroll
    for (int k = 0; k < K; k++) {
        float d    = fmaf(q[k], Ss, Sc) * cw[k]; // degree
        float cdis = cw[k] * rsqrtf(d);
        float g    = fmaf(bep, q[k], alp);
        r[k] = fmaf(g, cdis, a0);
    }
#pragma unroll
    for (int i = 0; i < 4; i++)
        out4[t + i * BLOCK] = make_float4(r[4*i], r[4*i+1], r[4*i+2], r[4*i+3]);
}

extern "C" void kernel_launch(void* const* d_in, const int* in_sizes, int n_in,
                              void* d_out, int out_size) {
    (void)in_sizes; (void)n_in; (void)out_size;
    const float4* in = (const float4*)d_in[0];
    float4* out = (float4*)d_out;
    spectral_rank2_kernel<<<1, BLOCK>>>(in, out);
}

// round 16
// speedup vs baseline: 1.0288x; 1.0288x over previous
#include <cuda_runtime.h>
#include <math.h>

#define BLOCK 256
#define K 16
#define NW (BLOCK / 32)      // 8 warps
#define FP_SCALE 65536.f     // 2^16 fixed-point scale (overflow-audited below)

// sm_103 integer REDUX: single-instruction warp reductions.
__device__ __forceinline__ int redux_add_s32(int v) {
    int r;
    asm volatile("redux.sync.add.s32 %0, %1, 0xffffffff;" : "=r"(r) : "r"(v));
    return r;
}
__device__ __forceinline__ unsigned redux_max_u32(unsigned v) {
    unsigned r;
    asm volatile("redux.sync.max.u32 %0, %1, 0xffffffff;" : "=r"(r) : "r"(v));
    return r;
}
__device__ __forceinline__ unsigned redux_min_u32(unsigned v) {
    unsigned r;
    asm volatile("redux.sync.min.u32 %0, %1, 0xffffffff;" : "=r"(r) : "r"(v));
    return r;
}

__global__ void __launch_bounds__(BLOCK, 1)
spectral_rank2_kernel(const float4* __restrict__ in4, float4* __restrict__ out4) {
    __shared__ int si[2][NW];        // fixed-point Sc, Ss warp partials
    __shared__ unsigned sq[2][NW];   // qmax, qmin warp partials (float bits)
    const int t = threadIdx.x;
    const int lane = t & 31, w = t >> 5;

    // ---- Phase 1: 4 x float4 loads (MLP=4) + feature transform.
    // sigmoid(|x|)=1/(1+e), v~=e, e=exp(-|x|); normalized feature direction
    // (1,q)/sqrt(1+q^2), q = e + e^2 > 0.
    float4 xv[4];
#pragma unroll
    for (int i = 0; i < 4; i++) xv[i] = in4[t + i * BLOCK];

    float q[K], cw[K];
    float pc = 0.f, ps = 0.f;
    unsigned pqmx = 0u, pqmn = 0xffffffffu;
#pragma unroll
    for (int k = 0; k < K; k++) {
        float x  = ((const float*)xv)[k];
        float e  = __expf(-fabsf(x));
        float qq = fmaf(e, e, e);                  // q = e + e^2
        float c  = rsqrtf(fmaf(qq, qq, 1.f));
        q[k] = qq; cw[k] = c;
        pc += c;
        ps = fmaf(qq, c, ps);
        unsigned qb = __float_as_uint(qq);
        pqmx = max(pqmx, qb);
        pqmn = min(pqmn, qb);
    }

    // ---- R1 (the only reduction round): fixed-point sums via REDUX.ADD.S32,
    // extremes via REDUX.{MAX,MIN}.U32 (positive-float bits are
    // order-isomorphic to u32). One barrier, two single-instruction levels.
    // Overflow audit: block totals <= 4096 -> level-2 value
    // <= 4 (replicas) * 4096 * 2^16 = 2^30 < INT32_MAX.
    {
        int ia = redux_add_s32(__float2int_rn(pc * FP_SCALE));
        int ib = redux_add_s32(__float2int_rn(ps * FP_SCALE));
        unsigned m = redux_max_u32(pqmx);
        unsigned n = redux_min_u32(pqmn);
        if (lane == 0) { si[0][w] = ia; si[1][w] = ib; sq[0][w] = m; sq[1][w] = n; }
    }
    __syncthreads();
    // Level 2: all 32 lanes read the 8 partials replicated 4x; REDUX sums the
    // replicas too -> total is 4x, folded into the 2^-18 constant. Integer
    // adds are order-independent -> fully deterministic across replays.
    const float Sc = (float)redux_add_s32(si[0][lane & 7]) * (0x1p-18f);
    const float Ss = (float)redux_add_s32(si[1][lane & 7]) * (0x1p-18f);
    const float qmx = __uint_as_float(redux_max_u32(sq[0][lane & 7]));
    const float qmn = __uint_as_float(redux_min_u32(sq[1][lane & 7]));

    // ---- Closed form (no further reductions): the rank-2 Gram matrix has
    // Perron eigenvector exactly (Sc, Ss) (identity: A*Sc+B*Ss=Sc,
    // B*Sc+G*Ss=Ss), so the Fiedler direction is the orthogonal complement
    // (al, be) = (-Ss, Sc). F(q) ∝ sin(θ-φ)/sqrt(cos(θ-φ)), θ = atan q —
    // strictly increasing, so extremes are at qmn/qmx (evaluated with the
    // identical op sequence for bit-consistent min/max).
    const float al = -Ss, be = Sc;
    float Fe[2];
    float qe[2] = {qmn, qmx};
#pragma unroll
    for (int k = 0; k < 2; k++) {
        float c    = rsqrtf(fmaf(qe[k], qe[k], 1.f));
        float d    = fmaf(qe[k], Ss, Sc) * c;
        float cdis = c * rsqrtf(d);
        Fe[k] = fmaf(be, qe[k], al) * cdis;
    }
    float Fmn = Fe[0], Fmx = Fe[1];              // monotone increasing in q
    float pivot = (fabsf(Fmx) >= fabsf(Fmn)) ? Fmx : Fmn;
    float sgn = (pivot >= 0.f) ? 1.f : -1.f;
    float mn = (sgn > 0.f) ? Fmn : -Fmx;
    float mx = (sgn > 0.f) ? Fmx : -Fmn;
    float scale = __fdividef(1.f, mx - mn + 1e-10f);
    float a1 = sgn * scale, a0 = -mn * scale;
    const float alp = al * a1, bep = be * a1;    // out = (bep*q+alp)*cdis + a0

    // ---- Epilogue: per-element Fiedler value + fused normalize + store.
    float r[K];
#pragma unroll
    for (int k = 0; k < K; k++) {
        float d    = fmaf(q[k], Ss, Sc) * cw[k]; // degree
        float cdis = cw[k] * rsqrtf(d);
        float g    = fmaf(bep, q[k], alp);
        r[k] = fmaf(g, cdis, a0);
    }
#pragma unroll
    for (int i = 0; i < 4; i++)
        out4[t + i * BLOCK] = make_float4(r[4*i], r[4*i+1], r[4*i+2], r[4*i+3]);
}

extern "C" void kernel_launch(void* const* d_in, const int* in_sizes, int n_in,
                              void* d_out, int out_size) {
    (void)in_sizes; (void)n_in; (void)out_size;
    const float4* in = (const float4*)d_in[0];
    float4* out = (float4*)d_out;
    spectral_rank2_kernel<<<1, BLOCK>>>(in, out);
}

// round 17
// speedup vs baseline: 1.0700x; 1.0400x over previous
#include <cuda_runtime.h>
#include <math.h>

#define BLOCK 256
#define K 16
#define NW (BLOCK / 32)      // 8 warps
#define FP_SCALE 65536.f     // 2^16 fixed-point scale (overflow-audited below)

// sm_103 integer REDUX: single-instruction warp reductions.
__device__ __forceinline__ int redux_add_s32(int v) {
    int r;
    asm volatile("redux.sync.add.s32 %0, %1, 0xffffffff;" : "=r"(r) : "r"(v));
    return r;
}
__device__ __forceinline__ unsigned redux_max_u32(unsigned v) {
    unsigned r;
    asm volatile("redux.sync.max.u32 %0, %1, 0xffffffff;" : "=r"(r) : "r"(v));
    return r;
}
__device__ __forceinline__ unsigned redux_min_u32(unsigned v) {
    unsigned r;
    asm volatile("redux.sync.min.u32 %0, %1, 0xffffffff;" : "=r"(r) : "r"(v));
    return r;
}

__global__ void __launch_bounds__(BLOCK, 1)
spectral_rank2_kernel(const float4* __restrict__ in4, float4* __restrict__ out4) {
    __shared__ int si[2][NW];        // fixed-point Sc, Ss warp partials
    __shared__ unsigned sq[2][NW];   // qmax, qmin warp partials (float bits)
    const int t = threadIdx.x;
    const int lane = t & 31, w = t >> 5;

    // ---- Phase 1: 4 x float4 loads (MLP=4) + feature transform.
    // sigmoid(|x|)=1/(1+e), v~=e, e=exp(-|x|); normalized feature direction
    // (1,q)/sqrt(1+q^2), q = e + e^2 > 0.
    float4 xv[4];
#pragma unroll
    for (int i = 0; i < 4; i++) xv[i] = in4[t + i * BLOCK];

    float q[K], cw[K];
    float pc = 0.f, ps = 0.f;
    unsigned pqmx = 0u, pqmn = 0xffffffffu;
#pragma unroll
    for (int k = 0; k < K; k++) {
        float x  = ((const float*)xv)[k];
        float e  = __expf(-fabsf(x));
        float qq = fmaf(e, e, e);                  // q = e + e^2
        float c  = rsqrtf(fmaf(qq, qq, 1.f));
        q[k] = qq; cw[k] = c;
        pc += c;
        ps = fmaf(qq, c, ps);
        unsigned qb = __float_as_uint(qq);
        pqmx = max(pqmx, qb);
        pqmn = min(pqmn, qb);
    }

    // ---- R1 (the only reduction round): fixed-point sums via REDUX.ADD.S32,
    // extremes via REDUX.{MAX,MIN}.U32 (positive-float bits are
    // order-isomorphic to u32). One barrier, two single-instruction levels.
    // Overflow audit: block totals <= 4096 -> level-2 value
    // <= 4 (replicas) * 4096 * 2^16 = 2^30 < INT32_MAX.
    {
        int ia = redux_add_s32(__float2int_rn(pc * FP_SCALE));
        int ib = redux_add_s32(__float2int_rn(ps * FP_SCALE));
        unsigned m = redux_max_u32(pqmx);
        unsigned n = redux_min_u32(pqmn);
        if (lane == 0) { si[0][w] = ia; si[1][w] = ib; sq[0][w] = m; sq[1][w] = n; }
    }
    __syncthreads();
    // Level 2: all 32 lanes read the 8 partials replicated 4x; REDUX sums the
    // replicas too -> total is 4x, folded into the 2^-18 constant. Integer
    // adds are order-independent -> fully deterministic across replays.
    const float Sc = (float)redux_add_s32(si[0][lane & 7]) * (0x1p-18f);
    const float Ss = (float)redux_add_s32(si[1][lane & 7]) * (0x1p-18f);
    const float qmx = __uint_as_float(redux_max_u32(sq[0][lane & 7]));
    const float qmn = __uint_as_float(redux_min_u32(sq[1][lane & 7]));

    // ---- Closed form (no further reductions): the rank-2 Gram matrix has
    // Perron eigenvector exactly (Sc, Ss) (identity: A*Sc+B*Ss=Sc,
    // B*Sc+G*Ss=Ss), so the Fiedler direction is the orthogonal complement
    // (al, be) = (-Ss, Sc). F(q) ∝ sin(θ-φ)/sqrt(cos(θ-φ)), θ = atan q —
    // strictly increasing, so extremes are at qmn/qmx (evaluated with the
    // identical op sequence for bit-consistent min/max).
    const float al = -Ss, be = Sc;
    float Fe[2];
    float qe[2] = {qmn, qmx};
#pragma unroll
    for (int k = 0; k < 2; k++) {
        float c    = rsqrtf(fmaf(qe[k], qe[k], 1.f));
        float d    = fmaf(qe[k], Ss, Sc) * c;
        float cdis = c * rsqrtf(d);
        Fe[k] = fmaf(be, qe[k], al) * cdis;
    }
    float Fmn = Fe[0], Fmx = Fe[1];              // monotone increasing in q
    float pivot = (fabsf(Fmx) >= fabsf(Fmn)) ? Fmx : Fmn;
    float sgn = (pivot >= 0.f) ? 1.f : -1.f;
    float mn = (sgn > 0.f) ? Fmn : -Fmx;
    float mx = (sgn > 0.f) ? Fmx : -Fmn;
    float scale = __fdividef(1.f, mx - mn + 1e-10f);
    float a1 = sgn * scale, a0 = -mn * scale;
    const float alp = al * a1, bep = be * a1;    // out = (bep*q+alp)*cdis + a0

    // ---- Epilogue: per-element Fiedler value + fused normalize + store.
    float r[K];
#pragma unroll
    for (int k = 0; k < K; k++) {
        float d    = fmaf(q[k], Ss, Sc) * cw[k]; // degree
        float cdis = cw[k] * rsqrtf(d);
        float g    = fmaf(bep, q[k], alp);
        r[k] = fmaf(g, cdis, a0);
    }
#pragma unroll
    for (int i = 0; i < 4; i++)
        out4[t + i * BLOCK] = make_float4(r[4*i], r[4*i+1], r[4*i+2], r[4*i+3]);
}

extern "C" void kernel_launch(void* const* d_in, const int* in_sizes, int n_in,
                              void* d_out, int out_size) {
    (void)in_sizes; (void)n_in; (void)out_size;
    const float4* in = (const float4*)d_in[0];
    float4* out = (float4*)d_out;
    spectral_rank2_kernel<<<1, BLOCK>>>(in, out);
}